// round 2
// baseline (speedup 1.0000x reference)
#include <cuda_runtime.h>
#include <cstdint>
#include <cstddef>

// Problem dims
#define HD    512
#define BATCH 1024
#define TSEQ  512
#define PLEN  96
#define DIN   32

// Persistent-kernel config
#define NCTA  128      // <= SM count: all CTAs co-resident, grid barrier is safe
#define BM    64       // batch rows per CTA tile
#define BN    64       // hidden cols per CTA tile (x3 gates)
#define BK    16       // k-slice

// -------- scratch (static device globals; no allocation allowed) --------
__device__ float    g_h1[2][BATCH * HD];
__device__ float    g_h2[2][BATCH * HD];
__device__ float    g_y[BATCH];
__device__ unsigned g_cnt;   // zero-initialized
__device__ unsigned g_gen;   // zero-initialized (generation counter; wraps safely)

// -------- packed fp32x2 helpers (Blackwell FFMA2 path, PTX-only) --------
#define PACKF2(o, l, h)   asm("mov.b64 %0,{%1,%2};" : "=l"(o) : "r"(l), "r"(h))
#define UNPACKF2(l, h, i) asm("mov.b64 {%0,%1},%2;" : "=r"(l), "=r"(h) : "l"(i))
#define FMAF2(c, a, b)    asm("fma.rn.f32x2 %0,%1,%2,%0;" : "+l"(c) : "l"(a), "l"(b))

struct SmemT {
    float  a[BK][BM + 4];     // [k][m]; row = 272B (16B multiple) so float4 reads align
    float2 b[BK][3][32];      // [k][gate][col_pair] = (col 2p, col 2p+1)
};

// ---------------------------------------------------------------------------
// Grid-wide barrier. All 128 CTAs are resident (grid <= SMs), so spinning is
// deadlock-free. Release: syncthreads -> thread0 fence.gpu -> atomic arrive.
// Acquire: spin on generation -> fence.gpu -> syncthreads.
// ---------------------------------------------------------------------------
__device__ __forceinline__ void gbar()
{
    __syncthreads();
    if (threadIdx.x == 0) {
        __threadfence();                                   // release all CTA writes
        unsigned gen = *(volatile unsigned*)&g_gen;        // read before arriving
        unsigned t = atomicAdd(&g_cnt, 1u);
        if (t == NCTA - 1) {
            *(volatile unsigned*)&g_cnt = 0;
            __threadfence();
            *(volatile unsigned*)&g_gen = gen + 1;
        } else {
            while (*(volatile unsigned*)&g_gen == gen) __nanosleep(32);
        }
        __threadfence();                                   // acquire (flushes L1)
    }
    __syncthreads();
}

// ---------------------------------------------------------------------------
// K-tiled GEMM accumulating 3 gate columns into f32x2 accumulators.
//   aR/aZ/aN[row][pairhalf] over cols (n0+2tx, n0+2tx+1) and (n0+32+2tx, +33).
// ---------------------------------------------------------------------------
__device__ __forceinline__ void gemm_acc(
    SmemT* sm, const float* __restrict__ A, int ldA,
    const float* __restrict__ W, int ldW, int K,
    int m0, int n0, int tid, int tx, int ty,
    unsigned long long (*aR)[2], unsigned long long (*aZ)[2],
    unsigned long long (*aN)[2])
{
    for (int kt = 0; kt < K; kt += BK) {
        __syncthreads();
        // A tile: 64 rows x 16 k (one float4/thread), stored transposed
        {
            const int r = tid >> 2, c4 = (tid & 3) << 2;
            const float4 v = *reinterpret_cast<const float4*>(
                A + (size_t)(m0 + r) * ldA + kt + c4);
            sm->a[c4 + 0][r] = v.x;
            sm->a[c4 + 1][r] = v.y;
            sm->a[c4 + 2][r] = v.z;
            sm->a[c4 + 3][r] = v.w;
        }
        // W tile: 3 gates x 64 cols x 16 k -> float2 col-pairs
#pragma unroll
        for (int ii = 0; ii < 3; ii++) {
            const int idx = tid + ii * 256;
            const int u = idx >> 2, c4 = (idx & 3) << 2;
            const int g = u >> 6, cc = u & 63, pp = cc >> 1, half = cc & 1;
            const float4 v = *reinterpret_cast<const float4*>(
                W + (size_t)(g * HD + n0 + cc) * ldW + kt + c4);
            reinterpret_cast<float*>(&sm->b[c4 + 0][g][pp])[half] = v.x;
            reinterpret_cast<float*>(&sm->b[c4 + 1][g][pp])[half] = v.y;
            reinterpret_cast<float*>(&sm->b[c4 + 2][g][pp])[half] = v.z;
            reinterpret_cast<float*>(&sm->b[c4 + 3][g][pp])[half] = v.w;
        }
        __syncthreads();
#pragma unroll
        for (int k = 0; k < BK; k++) {
            const float4 av = *reinterpret_cast<const float4*>(&sm->a[k][ty << 2]);
            unsigned long long a2[4];
            { uint32_t u0 = __float_as_uint(av.x); PACKF2(a2[0], u0, u0); }
            { uint32_t u1 = __float_as_uint(av.y); PACKF2(a2[1], u1, u1); }
            { uint32_t u2 = __float_as_uint(av.z); PACKF2(a2[2], u2, u2); }
            { uint32_t u3 = __float_as_uint(av.w); PACKF2(a2[3], u3, u3); }
            const unsigned long long b0a = *reinterpret_cast<unsigned long long*>(&sm->b[k][0][tx]);
            const unsigned long long b0b = *reinterpret_cast<unsigned long long*>(&sm->b[k][0][tx + 16]);
            const unsigned long long b1a = *reinterpret_cast<unsigned long long*>(&sm->b[k][1][tx]);
            const unsigned long long b1b = *reinterpret_cast<unsigned long long*>(&sm->b[k][1][tx + 16]);
            const unsigned long long b2a = *reinterpret_cast<unsigned long long*>(&sm->b[k][2][tx]);
            const unsigned long long b2b = *reinterpret_cast<unsigned long long*>(&sm->b[k][2][tx + 16]);
#pragma unroll
            for (int i = 0; i < 4; i++) {
                FMAF2(aR[i][0], a2[i], b0a); FMAF2(aR[i][1], a2[i], b0b);
                FMAF2(aZ[i][0], a2[i], b1a); FMAF2(aZ[i][1], a2[i], b1b);
                FMAF2(aN[i][0], a2[i], b2a); FMAF2(aN[i][1], a2[i], b2b);
            }
        }
    }
}

// ---------------------------------------------------------------------------
// Persistent kernel: entire encoder (512 steps) + decoder (96 steps).
// CTA tile: (blockIdx.x & 15) -> 64 batch rows, (blockIdx.x >> 4) -> 64 h cols.
// ---------------------------------------------------------------------------
__global__ void __launch_bounds__(256, 1) gru_persistent(
    const float* __restrict__ x,
    const float* __restrict__ eWih0, const float* __restrict__ eWhh0,
    const float* __restrict__ ebih0, const float* __restrict__ ebhh0,
    const float* __restrict__ eWih1, const float* __restrict__ eWhh1,
    const float* __restrict__ ebih1, const float* __restrict__ ebhh1,
    const float* __restrict__ dWih0, const float* __restrict__ dWhh0,
    const float* __restrict__ dbih0, const float* __restrict__ dbhh0,
    const float* __restrict__ dWih1, const float* __restrict__ dWhh1,
    const float* __restrict__ dbih1, const float* __restrict__ dbhh1,
    const float* __restrict__ outW,  const float* __restrict__ outb,
    const float* __restrict__ dstart, float* __restrict__ out)
{
    __shared__ SmemT sm;
    const int tid = threadIdx.x;
    const int tx = tid & 15, ty = tid >> 4;
    const int m0 = (blockIdx.x & 15) * BM;
    const int n0 = (blockIdx.x >> 4) * BN;

    // ---- init: zero parity-0 states, y = dec_start ----
    for (int i = blockIdx.x * 256 + tid; i < BATCH * HD; i += NCTA * 256) {
        g_h1[0][i] = 0.f; g_h2[0][i] = 0.f;
    }
    for (int i = blockIdx.x * 256 + tid; i < BATCH; i += NCTA * 256)
        g_y[i] = dstart[0];
    gbar();

    // ---- fused GRU cell: hidden GEMM + input GEMM (+scalar path) + gates ----
    auto cell = [&](const float* __restrict__ hprev, float* __restrict__ hout,
                    const float* __restrict__ Whh, const float* __restrict__ bhh,
                    const float* __restrict__ Ax, int ldx, int K2,
                    const float* __restrict__ Wih, int ldw,
                    const float* __restrict__ bih)
    {
        unsigned long long aR[4][2], aZ[4][2], aNH[4][2], aNI[4][2];
#pragma unroll
        for (int i = 0; i < 4; i++)
#pragma unroll
            for (int j = 0; j < 2; j++) { aR[i][j] = 0; aZ[i][j] = 0; aNH[i][j] = 0; aNI[i][j] = 0; }

        gemm_acc(&sm, hprev, HD, Whh, HD, HD, m0, n0, tid, tx, ty, aR, aZ, aNH);
        if (K2 >= BK)
            gemm_acc(&sm, Ax, ldx, Wih, ldw, K2, m0, n0, tid, tx, ty, aR, aZ, aNI);

#pragma unroll
        for (int i = 0; i < 4; i++) {
            const int m = m0 + (ty << 2) + i;
            const float yy = (K2 < BK) ? Ax[m] : 0.f;
#pragma unroll
            for (int j = 0; j < 2; j++) {
                const int cb = n0 + 2 * tx + (j ? 32 : 0);
                uint32_t l, h;
                float rv[2], zv[2], nh[2], ni[2];
                UNPACKF2(l, h, aR[i][j]);  rv[0] = __uint_as_float(l); rv[1] = __uint_as_float(h);
                UNPACKF2(l, h, aZ[i][j]);  zv[0] = __uint_as_float(l); zv[1] = __uint_as_float(h);
                UNPACKF2(l, h, aNH[i][j]); nh[0] = __uint_as_float(l); nh[1] = __uint_as_float(h);
                UNPACKF2(l, h, aNI[i][j]); ni[0] = __uint_as_float(l); ni[1] = __uint_as_float(h);
#pragma unroll
                for (int e = 0; e < 2; e++) {
                    const int col = cb + e;
                    float gr = rv[e], gz = zv[e], gn = ni[e];
                    if (K2 < BK) {   // decoder layer0: gi = y[b] * Wih[:,0]
                        gr += yy * Wih[col];
                        gz += yy * Wih[HD + col];
                        gn += yy * Wih[2 * HD + col];
                    }
                    const float rr = gr + bih[col] + bhh[col];
                    const float zz = gz + bih[HD + col] + bhh[HD + col];
                    const float r = 1.f / (1.f + expf(-rr));
                    const float z = 1.f / (1.f + expf(-zz));
                    const float n = tanhf(gn + bih[2 * HD + col] +
                                          r * (nh[e] + bhh[2 * HD + col]));
                    const float hp = hprev[(size_t)m * HD + col];
                    hout[(size_t)m * HD + col] = (1.f - z) * n + z * hp;
                }
            }
        }
    };

    int p = 0;
    // ---------------- encoder: 512 steps ----------------
    for (int t = 0; t < TSEQ; t++) {
        cell(g_h1[p], g_h1[1 - p], eWhh0, ebhh0,
             x + (size_t)t * DIN, TSEQ * DIN, DIN, eWih0, DIN, ebih0);
        gbar();
        cell(g_h2[p], g_h2[1 - p], eWhh1, ebhh1,
             g_h1[1 - p], HD, HD, eWih1, HD, ebih1);
        gbar();
        p ^= 1;
    }
    // ---------------- decoder: 96 steps ----------------
    for (int s = 0; s < PLEN; s++) {
        cell(g_h1[p], g_h1[1 - p], dWhh0, dbhh0,
             g_y, 1, 1, dWih0, 1, dbih0);
        gbar();
        cell(g_h2[p], g_h2[1 - p], dWhh1, dbhh1,
             g_h1[1 - p], HD, HD, dWih1, HD, dbih1);
        gbar();
        // projection: 8 rows per CTA, one warp each
        {
            const int w = tid >> 5, lane = tid & 31;
            const int row = blockIdx.x * 8 + w;
            const float* hr = g_h2[1 - p] + (size_t)row * HD;
            float ssum = 0.f;
#pragma unroll
            for (int q = 0; q < HD / 32; q++)
                ssum += hr[lane + 32 * q] * outW[lane + 32 * q];
#pragma unroll
            for (int o = 16; o > 0; o >>= 1)
                ssum += __shfl_xor_sync(0xffffffffu, ssum, o);
            if (lane == 0) {
                const float v = ssum + outb[0];
                g_y[row] = v;
                out[(size_t)row * PLEN + s] = v;
            }
        }
        gbar();
        p ^= 1;
    }
}

// ---------------------------------------------------------------------------
extern "C" void kernel_launch(void* const* d_in, const int* in_sizes, int n_in,
                              void* d_out, int out_size)
{
    const float* x      = (const float*)d_in[0];
    const float* eWih0  = (const float*)d_in[1];
    const float* eWhh0  = (const float*)d_in[2];
    const float* ebih0  = (const float*)d_in[3];
    const float* ebhh0  = (const float*)d_in[4];
    const float* eWih1  = (const float*)d_in[5];
    const float* eWhh1  = (const float*)d_in[6];
    const float* ebih1  = (const float*)d_in[7];
    const float* ebhh1  = (const float*)d_in[8];
    const float* dWih0  = (const float*)d_in[9];
    const float* dWhh0  = (const float*)d_in[10];
    const float* dbih0  = (const float*)d_in[11];
    const float* dbhh0  = (const float*)d_in[12];
    const float* dWih1  = (const float*)d_in[13];
    const float* dWhh1  = (const float*)d_in[14];
    const float* dbih1  = (const float*)d_in[15];
    const float* dbhh1  = (const float*)d_in[16];
    const float* outW   = (const float*)d_in[17];
    const float* outb   = (const float*)d_in[18];
    const float* dstart = (const float*)d_in[19];
    float* out = (float*)d_out;

    gru_persistent<<<NCTA, 256>>>(
        x,
        eWih0, eWhh0, ebih0, ebhh0,
        eWih1, eWhh1, ebih1, ebhh1,
        dWih0, dWhh0, dbih0, dbhh0,
        dWih1, dWhh1, dbih1, dbhh1,
        outW, outb, dstart, out);
}